// round 17
// baseline (speedup 1.0000x reference)
#include <cuda_runtime.h>

// CTC loss forward, two kernels.
// K1 (512 blocks x 256): block (b,seg) gathers+exps segment seg (32 rows) of
//   batch b into g_em[b][t][0..31]=exp(lp[t,b,c1(l)]), [32]=exp(blank).
//   Spreads the 540k scattered-line gather over all SMs with high MLP.
// K2 (64 blocks x 288): warp 0 = consumer (linear-domain fused-pair CTC
//   recursion off LDS, exact pow2 rescale every 4 steps via redux.sync.max.s32,
//   lag-applied). Warps 1-8 = copiers: preload ALL 32 of their g_em rows into
//   registers (one L2 round trip), then store segment s and bar.arrive s+1
//   (rows <= 32s+31 guaranteed), bar 9 after all. Consumer segment s waits
//   bar s+2; tail waits bar 9. smem has 1 pad row so quad loads never clamp.

constexpr int B_SZ  = 64;
constexpr int C_SZ  = 8000;
constexpr int L_MAX = 32;
constexpr int ROW   = 33;
constexpr int NTHR  = 288;

__device__ float g_em[B_SZ][256][ROW];   // 2.2MB, L2-resident between kernels
__device__ float g_loss[B_SZ];
__device__ int   g_count;

__device__ __forceinline__ int warp_max_s32(int v) {
    int r;
    asm volatile("redux.sync.max.s32 %0, %1, 0xffffffff;" : "=r"(r) : "r"(v));
    return r;
}
__device__ __forceinline__ float shup(float v, int d) {
    return __shfl_up_sync(0xffffffffu, v, d);
}

// ---------------- K1: gather + exp ----------------
__global__ void __launch_bounds__(256)
ctc_gather(const float* __restrict__ lp,
           const int*   __restrict__ targets,
           const int*   __restrict__ tgt_len) {
    const int b   = blockIdx.x >> 3;
    const int seg = blockIdx.x & 7;
    const int w   = threadIdx.x >> 5;
    const int l   = threadIdx.x & 31;
    const size_t BC = (size_t)B_SZ * C_SZ;

    const int tl = tgt_len[b];
    const int c1 = (l < tl) ? targets[b * L_MAX + l] : 0;
    const float* base = lp + (size_t)b * C_SZ;
    const int t0 = seg * 32 + w * 4;

    float v1[4], vb[4];
#pragma unroll
    for (int j = 0; j < 4; j++) {
        v1[j] = __ldg(base + (size_t)(t0 + j) * BC + c1);
        vb[j] = __ldg(base + (size_t)(t0 + j) * BC);
    }
#pragma unroll
    for (int j = 0; j < 4; j++) {
        g_em[b][t0 + j][l] = __expf(v1[j]);
        if (l == 0) g_em[b][t0 + j][32] = __expf(vb[j]);
    }
}

// ---------------- K2: copy + scan ----------------
struct QB { float p1[4], pb[4], pmA, pmB; };

__device__ __forceinline__ void loadq(const float* __restrict__ sm, int q,
                                      int l, float m0, QB& d) {
    const int r0 = 4 * q + 1;            // rows r0..r0+3; pad row covers 256
#pragma unroll
    for (int j = 0; j < 4; j++) {
        d.p1[j] = sm[(r0 + j) * ROW + l];
        d.pb[j] = sm[(r0 + j) * ROW + 32];
    }
    // l==0 reads [r*ROW-1] = previous row's blank slot; masked by m0
    d.pmA = sm[r0 * ROW + l - 1] * m0;
    d.pmB = sm[(r0 + 2) * ROW + l - 1] * m0;
}

__device__ __forceinline__ void do_quad(float& e, float& o, float& a2,
                                        const QB& c, float skf, float skfm,
                                        float m0, float m1) {
#pragma unroll
    for (int h = 0; h < 2; h++) {        // two fused pairs = 4 steps
        const float pm  = h ? c.pmB : c.pmA;
        const float p1a = c.p1[2 * h],     pba = c.pb[2 * h];
        const float p1b = c.p1[2 * h + 1], pbb = c.pb[2 * h + 1];
        const float x1  = shup(o, 1) * m0;
        const float x2  = shup(o, 2) * m1;
        const float y1  = shup(e, 1);
        const float otm = ((x1 + y1) + skfm * x2) * pm;
        const float et  = (e + x1) * pba;
        const float ot  = ((o + e) + skf * x1) * p1a;
        const float at  = (a2 + o) * pba;
        e  = (et + otm) * pbb;
        o  = ((ot + et) + skf * otm) * p1b;
        a2 = (at + ot) * pbb;
    }
}

__device__ __forceinline__ void rescale(float& e, float& o, float& a2,
                                        int& g, float& fpend, int& fexp) {
    e *= fpend; o *= fpend; a2 *= fpend; g += fexp;
    const int mi = warp_max_s32(__float_as_int(fmaxf(e, fmaxf(o, a2))));
    int fx = 207 - ((mi >> 23) & 0xff);              // 80 - E, exact pow2
    fx = fx > 127 ? 127 : (fx < -126 ? -126 : fx);
    fpend = __int_as_float((fx + 127) << 23);
    fexp  = fx;
}

__global__ void __launch_bounds__(NTHR, 1)
ctc_scan(const int* __restrict__ targets,
         const int* __restrict__ in_len,
         const int* __restrict__ tgt_len,
         float*     __restrict__ out) {
    __shared__ float sm[257 * ROW];                 // 256 rows + 1 pad row
    const int b   = blockIdx.x;
    const int tid = threadIdx.x;
    const int l   = tid & 31;
    const int w   = tid >> 5;

    const int tl   = tgt_len[b];
    const int last = in_len[b] - 1;                 // in [128, 255]

    if (w > 0) {
        // ---- copy warp pw: rows 32s + 4pw + j, all preloaded to registers ----
        const int pw = w - 1;
        float v1[8][4], vb[8][4];
#pragma unroll
        for (int s = 0; s < 8; s++)
#pragma unroll
            for (int j = 0; j < 4; j++) {
                const int t = 32 * s + 4 * pw + j;
                v1[s][j] = __ldcg(&g_em[b][t][l]);
                vb[s][j] = __ldcg(&g_em[b][t][32]);
            }
#pragma unroll
        for (int s = 0; s < 8; s++) {
#pragma unroll
            for (int j = 0; j < 4; j++) {
                const int t = 32 * s + 4 * pw + j;
                sm[t * ROW + l] = v1[s][j];
                if (l == 0) sm[t * ROW + 32] = vb[s][j];
            }
            asm volatile("bar.arrive %0, 288;" :: "r"(s + 1) : "memory");
        }
        asm volatile("bar.arrive 9, 288;" ::: "memory");
        return;
    }

    // ---- consumer warp ----
    const int  c1   = (l < tl) ? targets[b * L_MAX + l] : 0;
    const int  c1p  = __shfl_up_sync(0xffffffffu, c1, 1);
    const bool skip = (c1 != 0) && ((l == 0) || (c1 != c1p));
    const float skf  = skip ? 1.f : 0.f;
    const float skfm = shup(skf, 1);
    const float m0   = (l == 0) ? 0.f : 1.f;
    const float m1   = (l <= 1) ? 0.f : 1.f;

    asm volatile("bar.sync 1, 288;" ::: "memory");  // rows <= 31 available

    // t=0 init (prob domain, pre-scaled 2^80)
    float e = 0.f, o = 0.f, a2 = 0.f;
    if (l == 0) {
        e = sm[32] * 0x1p80f;
        o = (tl > 0) ? sm[0] * 0x1p80f : 0.f;
    }
    int g = 80;
    float fpend = 1.f;
    int   fexp  = 0;

    const int nq  = last >> 2;                      // in [32, 63]
    const int rem = last & 3;

    QB A, Bq;
    loadq(sm, 0, l, m0, A);

    int q = 0;
#pragma unroll 1
    for (int s = 0; s < 7; s++) {                   // 8-quad segments
        if (q + 1 >= nq) break;
        asm volatile("bar.sync %0, 288;" :: "r"(s + 2) : "memory");
        const int qend = min(nq, 8 * (s + 1));
        while (q + 1 < qend) {                      // quads in ping/pong pairs
            rescale(e, o, a2, g, fpend, fexp);      // every 4 steps, lagged
            loadq(sm, q + 1, l, m0, Bq);
            do_quad(e, o, a2, A, skf, skfm, m0, m1);  q++;
            rescale(e, o, a2, g, fpend, fexp);
            loadq(sm, q + 1, l, m0, A);
            do_quad(e, o, a2, Bq, skf, skfm, m0, m1); q++;
        }
    }
    asm volatile("bar.sync 9, 288;" ::: "memory");  // all rows ready
    while (q + 1 < nq) {
        rescale(e, o, a2, g, fpend, fexp);
        loadq(sm, q + 1, l, m0, Bq);
        do_quad(e, o, a2, A, skf, skfm, m0, m1);  q++;
        rescale(e, o, a2, g, fpend, fexp);
        loadq(sm, q + 1, l, m0, A);
        do_quad(e, o, a2, Bq, skf, skfm, m0, m1); q++;
    }
    if (q < nq) {                                   // leftover quad (nq odd)
        rescale(e, o, a2, g, fpend, fexp);
        loadq(sm, q + 1, l, m0, Bq);
        do_quad(e, o, a2, A, skf, skfm, m0, m1);  q++;
    }

    // epilogue: rem steps; quad-nq data sits in A (nq even) or Bq (nq odd)
    float ep1[3], epb[3];
#pragma unroll
    for (int j = 0; j < 3; j++) {
        ep1[j] = (nq & 1) ? Bq.p1[j] : A.p1[j];
        epb[j] = (nq & 1) ? Bq.pb[j] : A.pb[j];
    }
#pragma unroll
    for (int j = 0; j < 3; j++) {
        if (j < rem) {
            const float x1 = shup(o, 1) * m0;
            const float en = (e + x1) * epb[j];
            const float on = ((o + e) + skf * x1) * ep1[j];
            const float an = (a2 + o) * epb[j];
            e = en; o = on; a2 = an;
        }
    }

    // final states: i_blank = 2*tl (e @ lane tl, or a2 @ lane31 if tl==32),
    //               i_char  = 2*tl-1 (o @ lane tl-1)
    const float vbl = __shfl_sync(0xffffffffu, e, tl & 31);
    const float vbh = __shfl_sync(0xffffffffu, a2, 31);
    const float vb  = (tl >= 32) ? vbh : vbl;
    const int   icl = (tl > 0) ? (tl - 1) : 0;
    const float vc  = __shfl_sync(0xffffffffu, o, icl);
    const float tot = (tl > 0) ? (vb + vc) : vb;

    if (l == 0) {
        const float total_log = logf(tot) - (float)g * 0.69314718055994531f;
        const int   denom     = (tl > 0) ? tl : 1;
        g_loss[b] = -total_log / (float)denom;
        __threadfence();
        const int old = atomicAdd(&g_count, 1);
        if (old == B_SZ - 1) {
            g_count = 0;                            // reset for next graph replay
            __threadfence();
            float s = 0.f;
            for (int i = 0; i < B_SZ; i++) s += __ldcg((const float*)&g_loss[i]);
            out[0] = s / (float)B_SZ;
        }
    }
}

extern "C" void kernel_launch(void* const* d_in, const int* in_sizes, int n_in,
                              void* d_out, int out_size) {
    const float* log_probs  = (const float*)d_in[0];
    const int*   targets    = (const int*)d_in[1];
    const int*   input_len  = (const int*)d_in[2];
    const int*   target_len = (const int*)d_in[3];
    float* out = (float*)d_out;
    (void)in_sizes; (void)n_in; (void)out_size;

    ctc_gather<<<8 * B_SZ, 256>>>(log_probs, targets, target_len);
    ctc_scan<<<B_SZ, NTHR>>>(targets, input_len, target_len, out);
}